// round 1
// baseline (speedup 1.0000x reference)
#include <cuda_runtime.h>
#include <math.h>

#define NTOK 8192
#define CDIM 768
#define HDIM 3072
#define NEXP 16
#define TOPK 4
#define TILE_M 128
#define MAX_TILES 336
#define MAX_ROWS (MAX_TILES * TILE_M)
#define KT 16

// ---------------- device scratch (no allocations allowed) ----------------
__device__ float g_act[(size_t)MAX_ROWS * HDIM];      // SwiGLU activations
__device__ int   g_row_token[MAX_ROWS];
__device__ float g_row_weight[MAX_ROWS];
__device__ int   g_counts[NEXP];
__device__ int   g_cursor[NEXP];
__device__ int   g_offset[NEXP + 1];                  // [NEXP] = shared-expert offset
__device__ int   g_tile_expert[MAX_TILES];
__device__ int   g_tile_row0[MAX_TILES];
__device__ int   g_num_tiles;
__device__ int   g_topi[NTOK * TOPK];
__device__ float g_topw[NTOK * TOPK];

__device__ __forceinline__ float silu_f(float x) {
    return x / (1.0f + expf(-x));
}

// ---------------- init: zero output, counts, row arrays ----------------
__global__ void k_init(float* out, int out_n) {
    int i = blockIdx.x * blockDim.x + threadIdx.x;
    int stride = gridDim.x * blockDim.x;
    for (int j = i; j < out_n; j += stride) out[j] = 0.0f;
    for (int j = i; j < MAX_ROWS; j += stride) {
        g_row_token[j] = 0;
        g_row_weight[j] = 0.0f;
    }
    if (i < NEXP) g_counts[i] = 0;
}

// ---------------- gate: logits, sigmoid, top-4, counts ----------------
__global__ void k_gate(const float* __restrict__ x,
                       const float* __restrict__ wg,
                       const float* __restrict__ bias) {
    int warp = (blockIdx.x * blockDim.x + threadIdx.x) >> 5;
    int lane = threadIdx.x & 31;
    if (warp >= NTOK) return;
    const float* xr = x + (size_t)warp * CDIM;

    int e = lane & 15;
    int half = lane >> 4;
    float acc = 0.0f;
    int c0 = half * (CDIM / 2);
    for (int c = c0; c < c0 + CDIM / 2; ++c)
        acc += xr[c] * wg[c * NEXP + e];
    acc += __shfl_down_sync(0xFFFFFFFFu, acc, 16);

    float gate = -1.0f;
    if (lane < 16) gate = 1.0f / (1.0f + expf(-(acc + bias[e])));

    // rank among 16 experts (tie-break: lower index first, matches lax.top_k)
    int rank = 0;
    #pragma unroll
    for (int j = 0; j < 16; ++j) {
        float gj = __shfl_sync(0xFFFFFFFFu, gate, j);
        if (lane < 16) rank += (gj > gate) || (gj == gate && j < e);
    }
    bool selected = (lane < 16) && (rank < TOPK);

    float sv = selected ? gate : 0.0f;
    #pragma unroll
    for (int o = 8; o >= 1; o >>= 1)
        sv += __shfl_xor_sync(0xFFFFFFFFu, sv, o);

    unsigned ballot = __ballot_sync(0xFFFFFFFFu, selected);
    if (selected) {
        float w = gate / sv;
        int kidx = __popc(ballot & ((1u << lane) - 1u));
        g_topi[warp * TOPK + kidx] = e;
        g_topw[warp * TOPK + kidx] = w;
        atomicAdd(&g_counts[e], 1);
    }
}

// ---------------- scan: aligned segment offsets + tile map ----------------
__global__ void k_scan() {
    if (threadIdx.x != 0 || blockIdx.x != 0) return;
    int off = 0, nt = 0;
    for (int e = 0; e <= NEXP; ++e) {
        int cnt = (e < NEXP) ? g_counts[e] : NTOK;
        g_offset[e] = off;
        if (e < NEXP) g_cursor[e] = off;
        int tiles = (cnt + TILE_M - 1) / TILE_M;
        for (int i = 0; i < tiles; ++i) {
            g_tile_expert[nt] = e;
            g_tile_row0[nt] = off + i * TILE_M;
            nt++;
        }
        off += tiles * TILE_M;
    }
    g_num_tiles = nt;
}

// ---------------- fill: scatter tokens into compact rows ----------------
__global__ void k_fill() {
    int idx = blockIdx.x * blockDim.x + threadIdx.x;
    if (idx >= NTOK * (TOPK + 1)) return;
    int t = idx / (TOPK + 1);
    int j = idx % (TOPK + 1);
    if (j < TOPK) {
        int e = g_topi[t * TOPK + j];
        float w = g_topw[t * TOPK + j];
        int r = atomicAdd(&g_cursor[e], 1);
        g_row_token[r] = t;
        g_row_weight[r] = w;
    } else {
        int r = g_offset[NEXP] + t;   // shared expert: identity map, weight 1
        g_row_token[r] = t;
        g_row_weight[r] = 1.0f;
    }
}

// ---------------- FC1: act = swiglu(X_gathered @ Wfc) ----------------
// tile: 128 rows x 64 output cols; each output col j uses Wfc cols j and j+H
__global__ void __launch_bounds__(256) k_fc1(const float* __restrict__ x,
                                             const float* __restrict__ wsh,
                                             const float* __restrict__ wex) {
    int tile = blockIdx.x;
    if (tile >= g_num_tiles) return;
    int e = g_tile_expert[tile];
    int row0 = g_tile_row0[tile];
    int jb = blockIdx.y * 64;
    const float* wfc = (e == NEXP) ? wsh : wex + (size_t)e * CDIM * 2 * HDIM;

    __shared__ float As[KT][TILE_M];
    __shared__ float Bg[KT][64];
    __shared__ float Bv[KT][64];
    __shared__ int stok[TILE_M];

    int tid = threadIdx.x;
    if (tid < TILE_M) stok[tid] = g_row_token[row0 + tid];

    float accg[8][4];
    float accv[8][4];
    #pragma unroll
    for (int i = 0; i < 8; ++i)
        #pragma unroll
        for (int j = 0; j < 4; ++j) { accg[i][j] = 0.0f; accv[i][j] = 0.0f; }

    int tx = tid % 16;   // col group
    int ty = tid / 16;   // row group

    for (int k0 = 0; k0 < CDIM; k0 += KT) {
        __syncthreads();
        // A: 128 rows x 16 k (gathered), 512 float4, 2 per thread
        #pragma unroll
        for (int l = 0; l < 2; ++l) {
            int li = tid + l * 256;
            int m = li & 127;
            int kk4 = li >> 7;    // 0..3
            float4 av = *(const float4*)(x + (size_t)stok[m] * CDIM + k0 + kk4 * 4);
            As[kk4 * 4 + 0][m] = av.x;
            As[kk4 * 4 + 1][m] = av.y;
            As[kk4 * 4 + 2][m] = av.z;
            As[kk4 * 4 + 3][m] = av.w;
        }
        // B: 16 k rows x 64 cols, gate half + val half
        {
            int kk = tid / 16, c4 = tid % 16;
            const float* bsrc = wfc + (size_t)(k0 + kk) * (2 * HDIM) + jb + c4 * 4;
            float4 bgv = *(const float4*)bsrc;
            float4 bvv = *(const float4*)(bsrc + HDIM);
            *(float4*)&Bg[kk][c4 * 4] = bgv;
            *(float4*)&Bv[kk][c4 * 4] = bvv;
        }
        __syncthreads();

        #pragma unroll
        for (int kk = 0; kk < KT; ++kk) {
            float a[8];
            #pragma unroll
            for (int i = 0; i < 8; ++i) a[i] = As[kk][ty + 16 * i];
            float4 bg4 = *(float4*)&Bg[kk][tx * 4];
            float4 bv4 = *(float4*)&Bv[kk][tx * 4];
            float bg[4] = {bg4.x, bg4.y, bg4.z, bg4.w};
            float bv[4] = {bv4.x, bv4.y, bv4.z, bv4.w};
            #pragma unroll
            for (int i = 0; i < 8; ++i) {
                #pragma unroll
                for (int j = 0; j < 4; ++j) {
                    accg[i][j] += a[i] * bg[j];
                    accv[i][j] += a[i] * bv[j];
                }
            }
        }
    }

    #pragma unroll
    for (int i = 0; i < 8; ++i) {
        int m = ty + 16 * i;
        float4 o;
        o.x = silu_f(accg[i][0]) * accv[i][0];
        o.y = silu_f(accg[i][1]) * accv[i][1];
        o.z = silu_f(accg[i][2]) * accv[i][2];
        o.w = silu_f(accg[i][3]) * accv[i][3];
        *(float4*)&g_act[(size_t)(row0 + m) * HDIM + jb + tx * 4] = o;
    }
}

// ---------------- FC2: out[token] += weight * (act @ Wproj) ----------------
__global__ void __launch_bounds__(256) k_fc2(const float* __restrict__ wsh,
                                             const float* __restrict__ wex,
                                             float* __restrict__ out) {
    int tile = blockIdx.x;
    if (tile >= g_num_tiles) return;
    int e = g_tile_expert[tile];
    int row0 = g_tile_row0[tile];
    int cb = blockIdx.y * 64;
    const float* wproj = (e == NEXP) ? wsh : wex + (size_t)e * HDIM * CDIM;

    __shared__ float As[KT][TILE_M];
    __shared__ float Bs[KT][64];
    __shared__ int stok[TILE_M];
    __shared__ float sw[TILE_M];

    int tid = threadIdx.x;
    if (tid < TILE_M) {
        stok[tid] = g_row_token[row0 + tid];
        sw[tid] = g_row_weight[row0 + tid];
    }

    float acc[8][4];
    #pragma unroll
    for (int i = 0; i < 8; ++i)
        #pragma unroll
        for (int j = 0; j < 4; ++j) acc[i][j] = 0.0f;

    int tx = tid % 16;
    int ty = tid / 16;

    for (int k0 = 0; k0 < HDIM; k0 += KT) {
        __syncthreads();
        #pragma unroll
        for (int l = 0; l < 2; ++l) {
            int li = tid + l * 256;
            int m = li & 127;
            int kk4 = li >> 7;
            float4 av = *(const float4*)(&g_act[(size_t)(row0 + m) * HDIM + k0 + kk4 * 4]);
            As[kk4 * 4 + 0][m] = av.x;
            As[kk4 * 4 + 1][m] = av.y;
            As[kk4 * 4 + 2][m] = av.z;
            As[kk4 * 4 + 3][m] = av.w;
        }
        {
            int kk = tid / 16, c4 = tid % 16;
            float4 bv = *(const float4*)(wproj + (size_t)(k0 + kk) * CDIM + cb + c4 * 4);
            *(float4*)&Bs[kk][c4 * 4] = bv;
        }
        __syncthreads();

        #pragma unroll
        for (int kk = 0; kk < KT; ++kk) {
            float a[8];
            #pragma unroll
            for (int i = 0; i < 8; ++i) a[i] = As[kk][ty + 16 * i];
            float4 b4 = *(float4*)&Bs[kk][tx * 4];
            float b[4] = {b4.x, b4.y, b4.z, b4.w};
            #pragma unroll
            for (int i = 0; i < 8; ++i)
                #pragma unroll
                for (int j = 0; j < 4; ++j)
                    acc[i][j] += a[i] * b[j];
        }
    }

    #pragma unroll
    for (int i = 0; i < 8; ++i) {
        int m = ty + 16 * i;
        int t = stok[m];
        float w = sw[m];
        float* dst = out + (size_t)t * CDIM + cb + tx * 4;
        #pragma unroll
        for (int j = 0; j < 4; ++j)
            atomicAdd(dst + j, acc[i][j] * w);
    }
}

// ---------------- launch ----------------
extern "C" void kernel_launch(void* const* d_in, const int* in_sizes, int n_in,
                              void* d_out, int out_size) {
    const float* x              = (const float*)d_in[0];
    const float* w_shared_fc    = (const float*)d_in[1];
    const float* w_shared_proj  = (const float*)d_in[2];
    const float* w_experts_fc   = (const float*)d_in[3];
    const float* w_experts_proj = (const float*)d_in[4];
    const float* w_gate         = (const float*)d_in[5];
    const float* expert_bias    = (const float*)d_in[6];
    float* out = (float*)d_out;

    k_init<<<1024, 256>>>(out, out_size);
    k_gate<<<NTOK / 8, 256>>>(x, w_gate, expert_bias);
    k_scan<<<1, 32>>>();
    k_fill<<<(NTOK * (TOPK + 1) + 255) / 256, 256>>>();

    dim3 g1(MAX_TILES, HDIM / 64);
    k_fc1<<<g1, 256>>>(x, w_shared_fc, w_experts_fc);

    dim3 g2(MAX_TILES, CDIM / 64);
    k_fc2<<<g2, 256>>>(w_shared_proj, w_experts_proj, out);
}

// round 4
// speedup vs baseline: 3.5456x; 3.5456x over previous
#include <cuda_runtime.h>
#include <cstdint>
#include <math.h>

#define NTOK 8192
#define CDIM 768
#define HDIM 3072
#define H2   (2*HDIM)
#define NEXP 16
#define TOPK 4
#define TILE_M 128
#define MAX_TILES 336
#define MAX_ROWS (MAX_TILES*TILE_M)

#define KC 16
#define STAGES 4
#define BLK_N 256                  // gemm cols per CTA
#define FC1_NOUT 128               // swiglu outputs per CTA
#define FC1_COLS (HDIM/FC1_NOUT)   // 24
#define FC2_COLS (CDIM/BLK_N)      // 3
#define A_STG 2048                 // floats per stage: 128*16
#define B_STG 4096                 // 16*256
#define STG_FLOATS (A_STG + B_STG)
#define FC_SMEM (STAGES*STG_FLOATS*4)   // 96KB

// ------------------- device scratch -------------------
__device__ float g_xr[(size_t)NTOK*CDIM];
__device__ float g_wfc[(size_t)(NEXP+1)*CDIM*H2];
__device__ float g_wpj[(size_t)(NEXP+1)*HDIM*CDIM];
__device__ float g_act[(size_t)MAX_ROWS*HDIM];
__device__ float g_part[(size_t)MAX_ROWS*CDIM];
__device__ int   g_row_token[MAX_ROWS];
__device__ float g_row_weight[MAX_ROWS];
__device__ int   g_tok_rows[NTOK*(TOPK+1)];
__device__ int   g_counts[NEXP];
__device__ int   g_cursor[NEXP];
__device__ int   g_offset[NEXP+1];
__device__ int   g_tile_expert[MAX_TILES];
__device__ int   g_tile_row0[MAX_TILES];
__device__ int   g_num_tiles;
__device__ int   g_topi[NTOK*TOPK];
__device__ float g_topw[NTOK*TOPK];

// ------------------- helpers -------------------
__device__ __forceinline__ float to_tf32(float x){
    uint32_t u; asm("cvt.rna.tf32.f32 %0, %1;" : "=r"(u) : "f"(x));
    return __uint_as_float(u);
}
__device__ __forceinline__ float silu_f(float x){ return x / (1.0f + expf(-x)); }

__device__ __forceinline__ uint32_t smem_u32(const void* p){
    uint32_t a;
    asm("{ .reg .u64 t; cvta.to.shared.u64 t, %1; cvt.u32.u64 %0, t; }" : "=r"(a) : "l"(p));
    return a;
}

#define CP16(dst, src) \
    asm volatile("cp.async.cg.shared.global [%0], [%1], 16;" :: "r"(dst), "l"(src))
#define CP_COMMIT() asm volatile("cp.async.commit_group;")

__device__ __forceinline__ void mma_tf32(float* d, const uint32_t* a, const uint32_t* b){
    asm volatile(
        "mma.sync.aligned.m16n8k8.row.col.f32.tf32.tf32.f32 "
        "{%0,%1,%2,%3}, {%4,%5,%6,%7}, {%8,%9}, {%0,%1,%2,%3};"
        : "+f"(d[0]), "+f"(d[1]), "+f"(d[2]), "+f"(d[3])
        : "r"(a[0]), "r"(a[1]), "r"(a[2]), "r"(a[3]), "r"(b[0]), "r"(b[1]));
}

// ------------------- small kernels -------------------
__global__ void k_init(){
    int i = blockIdx.x*blockDim.x + threadIdx.x;
    int stride = gridDim.x*blockDim.x;
    for (int j = i; j < MAX_ROWS; j += stride) g_row_token[j] = 0;
    if (i < NEXP) g_counts[i] = 0;
}

__global__ void k_round_x(const float* __restrict__ x){
    int i = blockIdx.x*blockDim.x + threadIdx.x;
    int stride = gridDim.x*blockDim.x;
    for (int j = i; j < NTOK*CDIM; j += stride) g_xr[j] = to_tf32(x[j]);
}

__global__ void k_round_wfc(const float* __restrict__ wex, const float* __restrict__ wsh){
    int e = blockIdx.z;
    const float* src = (e == NEXP) ? wsh : wex + (size_t)e*CDIM*H2;
    float* dst = g_wfc + (size_t)e*CDIM*H2;
    const int n = CDIM*H2;
    for (int i = blockIdx.x*blockDim.x + threadIdx.x; i < n; i += gridDim.x*blockDim.x)
        dst[i] = to_tf32(src[i]);
}

__global__ void k_round_wpj(const float* __restrict__ wex, const float* __restrict__ wsh){
    int e = blockIdx.z;
    const float* src = (e == NEXP) ? wsh : wex + (size_t)e*HDIM*CDIM;
    float* dst = g_wpj + (size_t)e*HDIM*CDIM;
    const int n = HDIM*CDIM;
    for (int i = blockIdx.x*blockDim.x + threadIdx.x; i < n; i += gridDim.x*blockDim.x)
        dst[i] = to_tf32(src[i]);
}

__global__ void k_gate(const float* __restrict__ x,
                       const float* __restrict__ wg,
                       const float* __restrict__ bias){
    int warp = (blockIdx.x*blockDim.x + threadIdx.x) >> 5;
    int lane = threadIdx.x & 31;
    if (warp >= NTOK) return;
    const float* xr = x + (size_t)warp*CDIM;

    int e = lane & 15, half = lane >> 4;
    float acc = 0.0f;
    int c0 = half*(CDIM/2);
    for (int c = c0; c < c0 + CDIM/2; ++c) acc += xr[c]*wg[c*NEXP + e];
    acc += __shfl_down_sync(0xFFFFFFFFu, acc, 16);

    float gate = -1.0f;
    if (lane < 16) gate = 1.0f/(1.0f + expf(-(acc + bias[e])));

    int rank = 0;
    #pragma unroll
    for (int j = 0; j < 16; ++j){
        float gj = __shfl_sync(0xFFFFFFFFu, gate, j);
        if (lane < 16) rank += (gj > gate) || (gj == gate && j < e);
    }
    bool sel = (lane < 16) && (rank < TOPK);
    float sv = sel ? gate : 0.0f;
    #pragma unroll
    for (int o = 8; o >= 1; o >>= 1) sv += __shfl_xor_sync(0xFFFFFFFFu, sv, o);
    unsigned ballot = __ballot_sync(0xFFFFFFFFu, sel);
    if (sel){
        int kidx = __popc(ballot & ((1u << lane) - 1u));
        g_topi[warp*TOPK + kidx] = e;
        g_topw[warp*TOPK + kidx] = gate/sv;
        atomicAdd(&g_counts[e], 1);
    }
}

__global__ void k_scan(){
    if (threadIdx.x != 0 || blockIdx.x != 0) return;
    int off = 0, nt = 0;
    for (int e = 0; e <= NEXP; ++e){
        int cnt = (e < NEXP) ? g_counts[e] : NTOK;
        g_offset[e] = off;
        if (e < NEXP) g_cursor[e] = off;
        int tiles = (cnt + TILE_M - 1)/TILE_M;
        for (int i = 0; i < tiles; ++i){
            g_tile_expert[nt] = e;
            g_tile_row0[nt] = off + i*TILE_M;
            nt++;
        }
        off += tiles*TILE_M;
    }
    g_num_tiles = nt;
}

__global__ void k_fill(){
    int idx = blockIdx.x*blockDim.x + threadIdx.x;
    if (idx >= NTOK*(TOPK+1)) return;
    int t = idx/(TOPK+1), j = idx%(TOPK+1);
    if (j < TOPK){
        int e = g_topi[t*TOPK + j];
        float w = g_topw[t*TOPK + j];
        int r = atomicAdd(&g_cursor[e], 1);
        g_row_token[r] = t;
        g_row_weight[r] = w;
        g_tok_rows[t*(TOPK+1) + j] = r;
    } else {
        int r = g_offset[NEXP] + t;
        g_row_token[r] = t;
        g_row_weight[r] = 1.0f;
        g_tok_rows[t*(TOPK+1) + j] = r;
    }
}

// ------------------- FC1: swiglu(Xg @ Wfc) via mma.sync tf32 -------------------
// A swizzle: element (m,k) of A tile lives at m*16 + (k ^ (4*((m>>1)&3)))
// (mask confined to bits [2:3] -> never leaves the 16-float row)
__global__ void __launch_bounds__(512, 1) k_fc1(){
    int bx = blockIdx.x;
    int tile = bx / FC1_COLS, jb = (bx % FC1_COLS)*FC1_NOUT;
    if (tile >= g_num_tiles) return;
    int e = g_tile_expert[tile], row0 = g_tile_row0[tile];
    const float* wbase = g_wfc + (size_t)e*CDIM*H2;

    extern __shared__ float sm[];
    uint32_t sb = smem_u32(sm);

    int tid = threadIdx.x, lane = tid & 31, w = tid >> 5;
    int wm = w & 3, wn = w >> 2;
    int m0 = wm*32, n0 = wn*64;
    int r = lane >> 2, c = lane & 3;

    // cp.async assignments: 1 A chunk + 2 B chunks per thread
    int am = tid >> 2, akc = tid & 3;
    int tokA = g_row_token[row0 + am];
    const float* asrc = g_xr + (size_t)tokA*CDIM + akc*4;
    uint32_t adst = (uint32_t)(am*16 + ((akc*4) ^ (4*((am >> 1) & 3))))*4;

    const float* bsrc[2]; uint32_t bdst[2];
    #pragma unroll
    for (int i = 0; i < 2; i++){
        int p = tid + i*512;
        int bk = p >> 6, c0 = (p & 63)*4;
        int grp = c0 >> 3, off = c0 & 7;
        int srccol = (grp & 1) ? (HDIM + jb + (grp >> 1)*8 + off)
                               : (jb + (grp >> 1)*8 + off);
        bsrc[i] = wbase + (size_t)bk*H2 + srccol;
        bdst[i] = (uint32_t)(A_STG + bk*256 + (c0 ^ (8*(bk & 3))))*4;
    }

    #pragma unroll
    for (int s = 0; s < STAGES-1; s++){
        uint32_t so = sb + s*(STG_FLOATS*4);
        CP16(so + adst, asrc + s*KC);
        CP16(so + bdst[0], bsrc[0] + (size_t)s*KC*H2);
        CP16(so + bdst[1], bsrc[1] + (size_t)s*KC*H2);
        CP_COMMIT();
    }

    float acc[2][8][4];
    #pragma unroll
    for (int i = 0; i < 2; i++)
        #pragma unroll
        for (int j = 0; j < 8; j++)
            #pragma unroll
            for (int q = 0; q < 4; q++) acc[i][j][q] = 0.0f;

    // fragment address constants (read mask = 4*(r>>1))
    int xa = 4*(r >> 1);
    int ak[2][2];
    ak[0][0] = c ^ xa;        ak[0][1] = (c + 4) ^ xa;
    ak[1][0] = (8 + c) ^ xa;  ak[1][1] = (12 + c) ^ xa;
    int arow[4];
    #pragma unroll
    for (int j = 0; j < 4; j++) arow[j] = (m0 + j*8 + r)*16;
    int nx[8];
    #pragma unroll
    for (int ni = 0; ni < 8; ni++) nx[ni] = (n0 + r + 8*ni) ^ (8*c);
    int bkrow[2][2];
    bkrow[0][0] = A_STG + (c)*256;      bkrow[0][1] = A_STG + (c + 4)*256;
    bkrow[1][0] = A_STG + (8 + c)*256;  bkrow[1][1] = A_STG + (12 + c)*256;

    const int nK = CDIM/KC;   // 48
    for (int ks = 0; ks < nK; ks++){
        asm volatile("cp.async.wait_group %0;" :: "n"(STAGES-2) : "memory");
        __syncthreads();
        int t = ks + STAGES - 1;
        if (t < nK){
            uint32_t so = sb + (t % STAGES)*(STG_FLOATS*4);
            CP16(so + adst, asrc + t*KC);
            CP16(so + bdst[0], bsrc[0] + (size_t)t*KC*H2);
            CP16(so + bdst[1], bsrc[1] + (size_t)t*KC*H2);
        }
        CP_COMMIT();

        const uint32_t* As = (const uint32_t*)sm + (ks % STAGES)*STG_FLOATS;
        #pragma unroll
        for (int kb = 0; kb < 2; kb++){
            uint32_t a[2][4];
            #pragma unroll
            for (int mi = 0; mi < 2; mi++){
                a[mi][0] = As[arow[2*mi]     + ak[kb][0]];
                a[mi][1] = As[arow[2*mi + 1] + ak[kb][0]];
                a[mi][2] = As[arow[2*mi]     + ak[kb][1]];
                a[mi][3] = As[arow[2*mi + 1] + ak[kb][1]];
            }
            uint32_t b[8][2];
            #pragma unroll
            for (int ni = 0; ni < 8; ni++){
                b[ni][0] = As[bkrow[kb][0] + nx[ni]];
                b[ni][1] = As[bkrow[kb][1] + nx[ni]];
            }
            #pragma unroll
            for (int mi = 0; mi < 2; mi++)
                #pragma unroll
                for (int ni = 0; ni < 8; ni++)
                    mma_tf32(acc[mi][ni], a[mi], b[ni]);
        }
    }

    // epilogue: swiglu pairs (ni even = gate, ni+1 = val) within this warp
    int c2 = (lane & 3)*2;
    #pragma unroll
    for (int mi = 0; mi < 2; mi++){
        int ra = row0 + m0 + mi*16 + r;
        #pragma unroll
        for (int fe = 0; fe < 8; fe += 2){
            float* ag = acc[mi][fe];
            float* av = acc[mi][fe + 1];
            int ocol = jb + (4*wn + (fe >> 1))*8 + c2;
            float2 o0, o1;
            o0.x = to_tf32(silu_f(ag[0])*av[0]);
            o0.y = to_tf32(silu_f(ag[1])*av[1]);
            o1.x = to_tf32(silu_f(ag[2])*av[2]);
            o1.y = to_tf32(silu_f(ag[3])*av[3]);
            *(float2*)(g_act + (size_t)ra*HDIM + ocol) = o0;
            *(float2*)(g_act + (size_t)(ra + 8)*HDIM + ocol) = o1;
        }
    }
}

// ------------------- FC2: act @ Wproj -> g_part -------------------
__global__ void __launch_bounds__(512, 1) k_fc2(){
    int bx = blockIdx.x;
    int tile = bx / FC2_COLS, jb = (bx % FC2_COLS)*BLK_N;
    if (tile >= g_num_tiles) return;
    int e = g_tile_expert[tile], row0 = g_tile_row0[tile];
    const float* wbase = g_wpj + (size_t)e*HDIM*CDIM;

    extern __shared__ float sm[];
    uint32_t sb = smem_u32(sm);

    int tid = threadIdx.x, lane = tid & 31, w = tid >> 5;
    int wm = w & 3, wn = w >> 2;
    int m0 = wm*32, n0 = wn*64;
    int r = lane >> 2, c = lane & 3;

    int am = tid >> 2, akc = tid & 3;
    const float* asrc = g_act + (size_t)(row0 + am)*HDIM + akc*4;
    uint32_t adst = (uint32_t)(am*16 + ((akc*4) ^ (4*((am >> 1) & 3))))*4;

    const float* bsrc[2]; uint32_t bdst[2];
    #pragma unroll
    for (int i = 0; i < 2; i++){
        int p = tid + i*512;
        int bk = p >> 6, c0 = (p & 63)*4;
        bsrc[i] = wbase + (size_t)bk*CDIM + jb + c0;
        bdst[i] = (uint32_t)(A_STG + bk*256 + (c0 ^ (8*(bk & 3))))*4;
    }

    #pragma unroll
    for (int s = 0; s < STAGES-1; s++){
        uint32_t so = sb + s*(STG_FLOATS*4);
        CP16(so + adst, asrc + s*KC);
        CP16(so + bdst[0], bsrc[0] + (size_t)s*KC*CDIM);
        CP16(so + bdst[1], bsrc[1] + (size_t)s*KC*CDIM);
        CP_COMMIT();
    }

    float acc[2][8][4];
    #pragma unroll
    for (int i = 0; i < 2; i++)
        #pragma unroll
        for (int j = 0; j < 8; j++)
            #pragma unroll
            for (int q = 0; q < 4; q++) acc[i][j][q] = 0.0f;

    int xa = 4*(r >> 1);
    int ak[2][2];
    ak[0][0] = c ^ xa;        ak[0][1] = (c + 4) ^ xa;
    ak[1][0] = (8 + c) ^ xa;  ak[1][1] = (12 + c) ^ xa;
    int arow[4];
    #pragma unroll
    for (int j = 0; j < 4; j++) arow[j] = (m0 + j*8 + r)*16;
    int nx[8];
    #pragma unroll
    for (int ni = 0; ni < 8; ni++) nx[ni] = (n0 + r + 8*ni) ^ (8*c);
    int bkrow[2][2];
    bkrow[0][0] = A_STG + (c)*256;      bkrow[0][1] = A_STG + (c + 4)*256;
    bkrow[1][0] = A_STG + (8 + c)*256;  bkrow[1][1] = A_STG + (12 + c)*256;

    const int nK = HDIM/KC;   // 192
    for (int ks = 0; ks < nK; ks++){
        asm volatile("cp.async.wait_group %0;" :: "n"(STAGES-2) : "memory");
        __syncthreads();
        int t = ks + STAGES - 1;
        if (t < nK){
            uint32_t so = sb + (t % STAGES)*(STG_FLOATS*4);
            CP16(so + adst, asrc + t*KC);
            CP16(so + bdst[0], bsrc[0] + (size_t)t*KC*CDIM);
            CP16(so + bdst[1], bsrc[1] + (size_t)t*KC*CDIM);
        }
        CP_COMMIT();

        const uint32_t* As = (const uint32_t*)sm + (ks % STAGES)*STG_FLOATS;
        #pragma unroll
        for (int kb = 0; kb < 2; kb++){
            uint32_t a[2][4];
            #pragma unroll
            for (int mi = 0; mi < 2; mi++){
                a[mi][0] = As[arow[2*mi]     + ak[kb][0]];
                a[mi][1] = As[arow[2*mi + 1] + ak[kb][0]];
                a[mi][2] = As[arow[2*mi]     + ak[kb][1]];
                a[mi][3] = As[arow[2*mi + 1] + ak[kb][1]];
            }
            uint32_t b[8][2];
            #pragma unroll
            for (int ni = 0; ni < 8; ni++){
                b[ni][0] = As[bkrow[kb][0] + nx[ni]];
                b[ni][1] = As[bkrow[kb][1] + nx[ni]];
            }
            #pragma unroll
            for (int mi = 0; mi < 2; mi++)
                #pragma unroll
                for (int ni = 0; ni < 8; ni++)
                    mma_tf32(acc[mi][ni], a[mi], b[ni]);
        }
    }

    int c2 = (lane & 3)*2;
    #pragma unroll
    for (int mi = 0; mi < 2; mi++){
        int ra = row0 + m0 + mi*16 + r;
        #pragma unroll
        for (int ni = 0; ni < 8; ni++){
            int ocol = jb + n0 + ni*8 + c2;
            float2 o0, o1;
            o0.x = acc[mi][ni][0]; o0.y = acc[mi][ni][1];
            o1.x = acc[mi][ni][2]; o1.y = acc[mi][ni][3];
            *(float2*)(g_part + (size_t)ra*CDIM + ocol) = o0;
            *(float2*)(g_part + (size_t)(ra + 8)*CDIM + ocol) = o1;
        }
    }
}

// ------------------- gather: out[t] = sum_j w_j * part[r_j] -------------------
__global__ void k_gather(float* __restrict__ out){
    __shared__ int rs[TOPK+1];
    __shared__ float ws[TOPK+1];
    int t = blockIdx.x;
    if (threadIdx.x < TOPK+1){
        int r = g_tok_rows[t*(TOPK+1) + threadIdx.x];
        rs[threadIdx.x] = r;
        ws[threadIdx.x] = g_row_weight[r];
    }
    __syncthreads();
    int c = threadIdx.x*4;
    float4 acc = make_float4(0.f, 0.f, 0.f, 0.f);
    #pragma unroll
    for (int j = 0; j < TOPK+1; j++){
        const float4 p = *(const float4*)(g_part + (size_t)rs[j]*CDIM + c);
        float w = ws[j];
        acc.x += w*p.x; acc.y += w*p.y; acc.z += w*p.z; acc.w += w*p.w;
    }
    *(float4*)(out + (size_t)t*CDIM + c) = acc;
}

// ------------------- launch -------------------
extern "C" void kernel_launch(void* const* d_in, const int* in_sizes, int n_in,
                              void* d_out, int out_size){
    const float* x              = (const float*)d_in[0];
    const float* w_shared_fc    = (const float*)d_in[1];
    const float* w_shared_proj  = (const float*)d_in[2];
    const float* w_experts_fc   = (const float*)d_in[3];
    const float* w_experts_proj = (const float*)d_in[4];
    const float* w_gate         = (const float*)d_in[5];
    const float* expert_bias    = (const float*)d_in[6];
    float* out = (float*)d_out;

    cudaFuncSetAttribute(k_fc1, cudaFuncAttributeMaxDynamicSharedMemorySize, FC_SMEM);
    cudaFuncSetAttribute(k_fc2, cudaFuncAttributeMaxDynamicSharedMemorySize, FC_SMEM);

    k_init<<<512, 256>>>();
    k_round_x<<<2048, 256>>>(x);
    {
        dim3 g(2048, 1, NEXP+1);
        k_round_wfc<<<g, 256>>>(w_experts_fc, w_shared_fc);
        k_round_wpj<<<g, 256>>>(w_experts_proj, w_shared_proj);
    }
    k_gate<<<NTOK/8, 256>>>(x, w_gate, expert_bias);
    k_scan<<<1, 32>>>();
    k_fill<<<(NTOK*(TOPK+1) + 255)/256, 256>>>();

    k_fc1<<<MAX_TILES*FC1_COLS, 512, FC_SMEM>>>();
    k_fc2<<<MAX_TILES*FC2_COLS, 512, FC_SMEM>>>();
    k_gather<<<NTOK, CDIM/4>>>(out);
}